// round 10
// baseline (speedup 1.0000x reference)
#include <cuda_runtime.h>
#include <cuda_bf16.h>
#include <cuda_fp16.h>
#include <cstdint>

#define NN 50000
#define FE 128
#define NE 640000
#define GT 128            // GEMM tile rows per CTA
#define ST 68             // padded SMEM row stride (u32 units) — conflict-free

// ---------------------------------------------------------------------------
// Scratch (__device__ globals: allocation-free rule)
// ---------------------------------------------------------------------------
__device__ __half   d_Yh[(size_t)NN * FE];  // X @ W (fp16, gather operand)
__device__ int      d_head[NN];             // per-node linked-list head (edge id)
__device__ int      d_next[NE];             // next edge in chain (-1 terminates)

// ---------------------------------------------------------------------------
__device__ __forceinline__ void split_pair(float f0, float f1,
                                           uint32_t& hi, uint32_t& lo) {
    __nv_bfloat162 h2 = __floats2bfloat162_rn(f0, f1);
    float h0 = __bfloat162float(h2.x), h1 = __bfloat162float(h2.y);
    __nv_bfloat162 l2 = __floats2bfloat162_rn(f0 - h0, f1 - h1);
    hi = *(uint32_t*)&h2;
    lo = *(uint32_t*)&l2;
}

__device__ __forceinline__ void mma16816(float* c,
                                         uint32_t a0, uint32_t a1, uint32_t a2, uint32_t a3,
                                         uint32_t b0, uint32_t b1) {
    asm volatile(
        "mma.sync.aligned.m16n8k16.row.col.f32.bf16.bf16.f32 "
        "{%0,%1,%2,%3}, {%4,%5,%6,%7}, {%8,%9}, {%0,%1,%2,%3};"
        : "+f"(c[0]), "+f"(c[1]), "+f"(c[2]), "+f"(c[3])
        : "r"(a0), "r"(a1), "r"(a2), "r"(a3), "r"(b0), "r"(b1));
}

// ---------------------------------------------------------------------------
// GEMM via mma.sync bf16 3-term split; W converted inline (bf16 hi/lo).
// 256 thr (8 warps), 128-row tile, 4x2 warp tiling.
// Also initializes d_head for its 128 rows (build_kernel runs after).
// Epilogue: Y -> fp16 scratch, relu(Y) -> out[:, 0:128].
// ---------------------------------------------------------------------------
#define XH_OFF 0
#define XL_OFF 8704
#define WH_OFF 17408
#define WL_OFF 26112
#define SM_U32 34816
#define SM_BYTES (SM_U32 * 4)

__global__ __launch_bounds__(256, 1)
void gemm_tc_kernel(const float* __restrict__ X, const float* __restrict__ W,
                    float* __restrict__ out) {
    extern __shared__ uint32_t smu[];
    const int tid  = threadIdx.x;
    const int wid  = tid >> 5, lane = tid & 31;
    const int g    = lane >> 2, tig = lane & 3;
    const int row0 = blockIdx.x * GT;

    // init linked-list heads for this CTA's rows (covers all of d_head)
    if (tid < GT && row0 + tid < NN) d_head[row0 + tid] = -1;

    // Stage W: load fp32 (coalesced over n), split, store pair (2k,2k+1) at kp
    #pragma unroll
    for (int i = 0; i < 32; ++i) {
        int q  = i * 256 + tid;         // 8192 items
        int kp = q >> 7, n = q & 127;
        float w0 = W[(2 * kp)     * FE + n];
        float w1 = W[(2 * kp + 1) * FE + n];
        uint32_t hi, lo;
        split_pair(w0, w1, hi, lo);
        smu[WH_OFF + n * ST + kp] = hi;
        smu[WL_OFF + n * ST + kp] = lo;
    }
    // Stage X tile: load fp32, split to bf16 hi/lo pairs
    #pragma unroll
    for (int i = 0; i < 16; ++i) {
        int q  = i * 256 + tid;
        int r  = q >> 5, c4 = q & 31;
        float4 v = make_float4(0.f, 0.f, 0.f, 0.f);
        if (row0 + r < NN) v = ((const float4*)X)[(size_t)(row0 + r) * 32 + c4];
        uint32_t h01, l01, h23, l23;
        split_pair(v.x, v.y, h01, l01);
        split_pair(v.z, v.w, h23, l23);
        uint32_t o = r * ST + c4 * 2;
        smu[XH_OFF + o]     = h01;
        smu[XH_OFF + o + 1] = h23;
        smu[XL_OFF + o]     = l01;
        smu[XL_OFF + o + 1] = l23;
    }
    __syncthreads();

    const int rw = (wid & 3) * 32;
    const int cw = (wid >> 2) * 64;

    float acc[2][8][4];
    #pragma unroll
    for (int t = 0; t < 2; ++t)
        #pragma unroll
        for (int j = 0; j < 8; ++j)
            #pragma unroll
            for (int q = 0; q < 4; ++q) acc[t][j][q] = 0.f;

    #pragma unroll
    for (int ks = 0; ks < 8; ++ks) {
        const int kb = ks * 8;
        uint32_t ah[2][4], al[2][4];
        #pragma unroll
        for (int t = 0; t < 2; ++t) {
            uint32_t r0 = (rw + t * 16 + g) * ST + kb + tig;
            uint32_t r8 = r0 + 8 * ST;
            ah[t][0] = smu[XH_OFF + r0];
            ah[t][1] = smu[XH_OFF + r8];
            ah[t][2] = smu[XH_OFF + r0 + 4];
            ah[t][3] = smu[XH_OFF + r8 + 4];
            al[t][0] = smu[XL_OFF + r0];
            al[t][1] = smu[XL_OFF + r8];
            al[t][2] = smu[XL_OFF + r0 + 4];
            al[t][3] = smu[XL_OFF + r8 + 4];
        }
        #pragma unroll
        for (int j = 0; j < 8; ++j) {
            uint32_t bo  = (cw + j * 8 + g) * ST + kb + tig;
            uint32_t bh0 = smu[WH_OFF + bo];
            uint32_t bh1 = smu[WH_OFF + bo + 4];
            uint32_t bl0 = smu[WL_OFF + bo];
            uint32_t bl1 = smu[WL_OFF + bo + 4];
            #pragma unroll
            for (int t = 0; t < 2; ++t) {
                mma16816(acc[t][j], ah[t][0], ah[t][1], ah[t][2], ah[t][3], bh0, bh1);
                mma16816(acc[t][j], ah[t][0], ah[t][1], ah[t][2], ah[t][3], bl0, bl1);
                mma16816(acc[t][j], al[t][0], al[t][1], al[t][2], al[t][3], bh0, bh1);
            }
        }
    }

    #pragma unroll
    for (int t = 0; t < 2; ++t) {
        #pragma unroll
        for (int j = 0; j < 8; ++j) {
            int col = cw + j * 8 + tig * 2;
            #pragma unroll
            for (int h = 0; h < 2; ++h) {
                int r = row0 + rw + t * 16 + g + h * 8;
                if (r < NN) {
                    float y0 = acc[t][j][h * 2], y1 = acc[t][j][h * 2 + 1];
                    *(__half2*)&d_Yh[(size_t)r * FE + col] =
                        __float22half2_rn(make_float2(y0, y1));
                    *(float2*)&out[(size_t)r * 256 + col] =
                        make_float2(fmaxf(y0, 0.f), fmaxf(y1, 0.f));
                }
            }
        }
    }
}

// ---------------------------------------------------------------------------
// build: atomic-push linked lists. 8 edges / thread.
// Race note: next[e] stored after exch is safe — readers run in a later kernel.
// ---------------------------------------------------------------------------
__global__ void build_kernel(const int* __restrict__ edst) {
    int i = blockIdx.x * blockDim.x + threadIdx.x;
    if (i < NE / 8) {
        int4 a = ((const int4*)edst)[2 * i];
        int4 b = ((const int4*)edst)[2 * i + 1];
        int e0 = i * 8;
        int4 na, nb;
        na.x = atomicExch(&d_head[a.x], e0 + 0);
        na.y = atomicExch(&d_head[a.y], e0 + 1);
        na.z = atomicExch(&d_head[a.z], e0 + 2);
        na.w = atomicExch(&d_head[a.w], e0 + 3);
        nb.x = atomicExch(&d_head[b.x], e0 + 4);
        nb.y = atomicExch(&d_head[b.y], e0 + 5);
        nb.z = atomicExch(&d_head[b.z], e0 + 6);
        nb.w = atomicExch(&d_head[b.w], e0 + 7);
        ((int4*)d_next)[2 * i]     = na;
        ((int4*)d_next)[2 * i + 1] = nb;
    }
}

// ---------------------------------------------------------------------------
// agg: one warp walks 2 node chains (interleaved for MLP); fp16 gather,
// fp32 accum; degree counted during the walk; relu(mean) -> out[:, 128:].
// Chain loads (head/next/esrc) are warp-uniform -> broadcast.
// ---------------------------------------------------------------------------
__global__ __launch_bounds__(256)
void agg_kernel(const int* __restrict__ esrc, float* __restrict__ out) {
    int w    = (blockIdx.x * blockDim.x + threadIdx.x) >> 5;
    int lane = threadIdx.x & 31;
    int n0   = w * 2;
    if (n0 >= NN) return;
    int n1 = n0 + 1;   // NN even -> always valid

    int e0 = d_head[n0];
    int e1 = d_head[n1];
    float4 a0c = make_float4(0.f, 0.f, 0.f, 0.f);
    float4 a1c = make_float4(0.f, 0.f, 0.f, 0.f);
    int deg0 = 0, deg1 = 0;

    while ((e0 | e1) >= 0 || e0 >= 0 || e1 >= 0) {
        int nx0 = -1, nx1 = -1, s0 = 0, s1 = 0;
        if (e0 >= 0) { nx0 = d_next[e0]; s0 = esrc[e0]; }
        if (e1 >= 0) { nx1 = d_next[e1]; s1 = esrc[e1]; }
        if (e0 >= 0) {
            uint2 u = ((const uint2*)(d_Yh + (size_t)s0 * FE))[lane];
            float2 a = __half22float2(*(__half2*)&u.x);
            float2 b = __half22float2(*(__half2*)&u.y);
            a0c.x += a.x; a0c.y += a.y; a0c.z += b.x; a0c.w += b.y;
            ++deg0;
        }
        if (e1 >= 0) {
            uint2 u = ((const uint2*)(d_Yh + (size_t)s1 * FE))[lane];
            float2 a = __half22float2(*(__half2*)&u.x);
            float2 b = __half22float2(*(__half2*)&u.y);
            a1c.x += a.x; a1c.y += a.y; a1c.z += b.x; a1c.w += b.y;
            ++deg1;
        }
        e0 = (e0 >= 0) ? nx0 : -1;
        e1 = (e1 >= 0) ? nx1 : -1;
    }

    float inv0 = (deg0 > 0) ? (1.0f / (float)deg0) : 0.0f;
    float inv1 = (deg1 > 0) ? (1.0f / (float)deg1) : 0.0f;
    float4 r0 = make_float4(fmaxf(a0c.x * inv0, 0.f), fmaxf(a0c.y * inv0, 0.f),
                            fmaxf(a0c.z * inv0, 0.f), fmaxf(a0c.w * inv0, 0.f));
    float4 r1 = make_float4(fmaxf(a1c.x * inv1, 0.f), fmaxf(a1c.y * inv1, 0.f),
                            fmaxf(a1c.z * inv1, 0.f), fmaxf(a1c.w * inv1, 0.f));
    ((float4*)(out + (size_t)n0 * 256 + 128))[lane] = r0;
    ((float4*)(out + (size_t)n1 * 256 + 128))[lane] = r1;
}

// ---------------------------------------------------------------------------
extern "C" void kernel_launch(void* const* d_in, const int* in_sizes, int n_in,
                              void* d_out, int out_size) {
    const float* X    = (const float*)d_in[0];
    const float* W    = (const float*)d_in[1];
    const int*   edst = (const int*)d_in[2];
    const int*   esrc = (const int*)d_in[3];
    float*       out  = (float*)d_out;

    cudaFuncSetAttribute(gemm_tc_kernel,
                         cudaFuncAttributeMaxDynamicSharedMemorySize, SM_BYTES);

    gemm_tc_kernel<<<(NN + GT - 1) / GT, 256, SM_BYTES>>>(X, W, out);  // also inits d_head
    build_kernel<<<(NE / 8 + 255) / 256, 256>>>(edst);
    agg_kernel<<<((NN / 2) * 32 + 255) / 256, 256>>>(esrc, out);
}